// round 14
// baseline (speedup 1.0000x reference)
#include <cuda_runtime.h>
#include <cstdint>

// RotaryEmbedding2D: R[b, s, 64, 64] fp32, 16384 matrices of 16 KB each.
// Per matrix: 32 diagonal 2x2 rotation blocks (128 nonzero floats), zeros
// elsewhere; nonzero locations identical across matrices.
//
// Converged champion family, flattest form: one CTA (1024 threads) per
// matrix, exactly one float4 slot per thread. Match decode is a single
// compare; the (sin,cos) pair is selected in-register; each thread issues
// exactly one st.global.cs.v4 (evict-first — measured best policy: default
// LRU +1.6us writeback scheduling, .wt +2.8us unmerged sectors). Kernel is
// pinned at the path-independent DRAM write ceiling (~6.8 TB/s steady
// state), verified invariant across TMA-bulk / STG.v4 / STG.v8 paths.

static constexpr unsigned THREADS = 1024;

__global__ void __launch_bounds__(THREADS) rope2d_kernel(
    const float* __restrict__ spa,   // (n_mat, 2)
    float4* __restrict__ out)        // (n_mat, 1024) float4 view
{
    unsigned tid = threadIdx.x;
    unsigned bs  = blockIdx.x;

    // ---- match decode: slot w = tid -> row = tid>>4, f4col = tid&15.
    // Pair lives at f4col == row>>2 = tid>>6.
    unsigned row  = tid >> 4;                       // 0..63
    bool    match = (tid & 15u) == (tid >> 6);

    // ---- pair value (zeros when no match) ----------------------------------
    float4 v = make_float4(0.f, 0.f, 0.f, 0.f);
    if (match) {
        float2 xy = *reinterpret_cast<const float2*>(spa + (size_t)bs * 2u);
        unsigned h = row >> 1;                      // 0..31
        float coord = (h & 16u) ? xy.y : xy.x;
        // inv_freq = 10000^(-(h%16)/16) = 2^(-(h%16)*log2(10000)/16)
        float invf = exp2f(-(float)(h & 15u) * (13.287712379549449f / 16.0f));
        float s, c;
        __sincosf(coord * invf, &s, &c);
        float a, b;
        if (row & 1u) { a = s; b = c;  }            // odd row:  (sin, cos)
        else          { a = c; b = -s; }            // even row: (cos, -sin)
        if (row & 2u) { v.z = a; v.w = b; }         // pair at lanes 2,3
        else          { v.x = a; v.y = b; }         // pair at lanes 0,1
    }

    // ---- exactly one streaming store per thread ----------------------------
    __stcs(out + (size_t)bs * 1024u + tid, v);      // st.global.cs.v4
}

extern "C" void kernel_launch(void* const* d_in, const int* in_sizes, int n_in,
                              void* d_out, int out_size)
{
    const float* spa = (const float*)d_in[0];
    float4* out = (float4*)d_out;

    unsigned n_mat = (unsigned)(out_size / 4096);   // 16384
    rope2d_kernel<<<n_mat, THREADS>>>(spa, out);
}

// round 15
// speedup vs baseline: 1.2070x; 1.2070x over previous
#include <cuda_runtime.h>
#include <cstdint>

// RotaryEmbedding2D: R[b, s, 64, 64] fp32, 16384 matrices of 16 KB each.
// Per matrix: 32 diagonal 2x2 rotation blocks (128 nonzero floats), zeros
// elsewhere; nonzero locations identical across matrices.
//
// FINAL — round-13 champion (39.39 us, session best). One CTA (512 threads)
// per matrix; each thread owns float4 slots tid + 512k (k=0..1): two
// unconditional coalesced zero stores plus at most one predicated
// (sin,cos)-pair overwrite to the same address (same-thread program order
// guarantees the pair lands). All stores st.global.cs (evict-first).
//
// Measured design space (all axes swept):
//   store path:  TMA-bulk 41.0 | STG.v4 39.4 | STG.v8 39.4  -> path-indep
//   L2 policy:   default 41.0 | .cs 39.4 | .wt 42.2          -> .cs best
//   shape:       256x4 39.4-40.1 | 512x2 39.39 | 1024x1 47.6 -> 512x2 best
//   persistent TMA pipelines: 46.9-55.8                      -> rejected
// Pinned at the path-independent DRAM write ceiling (~6.8 TB/s steady
// state), ~95% of the ~37.5 us theoretical floor for the 268 MB stream.

static constexpr unsigned THREADS = 512;

__global__ void __launch_bounds__(THREADS) rope2d_kernel(
    const float* __restrict__ spa,   // (n_mat, 2)
    float4* __restrict__ out)        // (n_mat, 1024) float4 view
{
    unsigned tid = threadIdx.x;
    unsigned bs  = blockIdx.x;

    // ---- match decode: slot w = tid + 512k (k=0..1) -> row = 32k + (tid>>4),
    // f4col = tid & 15. Pair slot iff f4col == row>>2 = 8k + (tid>>6).
    int      diff = (int)(tid & 15u) - (int)(tid >> 6);
    bool   match  = (diff == 0) || (diff == 8);
    unsigned km   = (unsigned)diff >> 3;            // matching k (0..1)
    unsigned row  = 32u * km + (tid >> 4);          // matched output row

    // ---- pair value (meaningful only when match) ---------------------------
    float4 pv = make_float4(0.f, 0.f, 0.f, 0.f);
    if (match) {
        float2 xy = *reinterpret_cast<const float2*>(spa + (size_t)bs * 2u);
        unsigned h = row >> 1;                      // 0..31
        float coord = (h & 16u) ? xy.y : xy.x;
        // inv_freq = 10000^(-(h%16)/16) = 2^(-(h%16)*log2(10000)/16)
        float invf = exp2f(-(float)(h & 15u) * (13.287712379549449f / 16.0f));
        float s, c;
        __sincosf(coord * invf, &s, &c);
        float a, b;
        if (row & 1u) { a = s; b = c;  }            // odd row:  (sin, cos)
        else          { a = c; b = -s; }            // even row: (cos, -sin)
        if (row & 2u) { pv.z = a; pv.w = b; }       // pair at lanes 2,3
        else          { pv.x = a; pv.y = b; }       // pair at lanes 0,1
    }

    // ---- 2 unconditional streaming zero stores + 1 predicated overwrite ----
    const float4 z = make_float4(0.f, 0.f, 0.f, 0.f);
    float4* base = out + (size_t)bs * 1024u + tid;
    __stcs(base,        z);                         // slot tid
    __stcs(base + 512u, z);                         // slot tid + 512
    if (match)
        __stcs(base + 512u * km, pv);               // same addr, ordered after zero
}

extern "C" void kernel_launch(void* const* d_in, const int* in_sizes, int n_in,
                              void* d_out, int out_size)
{
    const float* spa = (const float*)d_in[0];
    float4* out = (float4*)d_out;

    unsigned n_mat = (unsigned)(out_size / 4096);   // 16384
    rope2d_kernel<<<n_mat, THREADS>>>(spa, out);
}